// round 17
// baseline (speedup 1.0000x reference)
#include <cuda_runtime.h>

#define N_NODES 50000
#define N_EDGES 800000
#define CAP     64            // per-node bucket capacity (P(deg>64) ~ 2e-18)

// ---------------- scratch (no allocation allowed) ----------------
__device__ float g_agg[N_NODES * 128];   // layer-1 aggregated x
__device__ float g_P2 [N_NODES * 128];   // [h@W2l^T | h@W2r^T]
__device__ int   g_cnt[N_NODES];         // per-node fill counts (= degree)
__device__ int   g_elist[N_NODES * CAP]; // bucketed src lists
__device__ float g_B1[256 * 128];        // [W1l;W1r]^T k-major (K=256), tf32
__device__ float g_B2[128 * 128];        // [W2l;W2r]^T k-major (K=128), tf32

// ---------------- tf32 helper ----------------
__device__ __forceinline__ float tf32r(float x) {
    unsigned r;
    asm("cvt.rna.tf32.f32 %0, %1;" : "=r"(r) : "f"(x));
    return __uint_as_float(r);
}

// ---------------- weight prep: concatenated k-major B (tf32) --------------
__global__ void prep_weights(const float* __restrict__ W1l, const float* __restrict__ W1r,
                             const float* __restrict__ W2l, const float* __restrict__ W2r) {
    int t = blockIdx.x * blockDim.x + threadIdx.x;
    if (t < 256 * 128) {
        int k = t >> 7, o = t & 127;
        float v = (k < 128) ? W1l[o * 128 + k] : W1r[o * 128 + (k - 128)];
        g_B1[t] = tf32r(v);
    }
    int t2 = t - 256 * 128;
    if (t2 >= 0 && t2 < 128 * 128) {
        int k = t2 >> 7, o = t2 & 127;
        float v = (o < 64) ? W2l[o * 128 + k] : W2r[(o - 64) * 128 + k];
        g_B2[t2] = tf32r(v);
    }
}

// ---------------- single-pass bucketed CSR fill ----------------
__global__ void fill_buckets(const int* __restrict__ ei) {
    int e = blockIdx.x * blockDim.x + threadIdx.x;
    if (e < N_EDGES) {
        int dst = __ldg(&ei[N_EDGES + e]);
        int p = atomicAdd(&g_cnt[dst], 1);
        if (p < CAP) g_elist[dst * CAP + p] = __ldg(&ei[e]);
    }
}

// ---------------- layer-1 aggregation: warp per node, 128-wide ------------
__global__ void aggregate(const float* __restrict__ x_ext) {
    int t = blockIdx.x * blockDim.x + threadIdx.x;
    int w = t >> 5;
    int lane = t & 31;
    if (w >= N_NODES) return;
    int off = w * CAP;
    int d = g_cnt[w];
    int dr = min(d, CAP);
    float4 s = make_float4(0.f, 0.f, 0.f, 0.f);
#pragma unroll 4
    for (int i = 0; i < dr; i++) {
        int src = __ldg(&g_elist[off + i]);
        float4 v = *(const float4*)(x_ext + (size_t)src * 128 + lane * 4);
        s.x += v.x; s.y += v.y; s.z += v.z; s.w += v.w;
    }
    float inv = (d > 0) ? (1.f / (float)d) : 0.f;
    s.x *= inv; s.y *= inv; s.z *= inv; s.w *= inv;
    *(float4*)(g_agg + (size_t)w * 128 + lane * 4) = s;
}

// ------ layer-2 fused aggregate: out = agg(P2[:, :64])/deg + P2[w,64:]+b --
__global__ void aggregate_out(const float* __restrict__ bias,
                              float* __restrict__ outp) {
    int t = blockIdx.x * blockDim.x + threadIdx.x;
    int w = t >> 5;
    int lane = t & 31;
    if (w >= N_NODES) return;
    int off = w * CAP;
    int d = g_cnt[w];
    int dr = min(d, CAP);
    int half = lane >> 4;             // 0 or 1
    int sub  = lane & 15;
    const float* basep = g_P2 + sub * 4;
    float4 s = make_float4(0.f, 0.f, 0.f, 0.f);
    int i = 0;
#pragma unroll 2
    for (; i + 2 <= dr; i += 2) {
        int src = __ldg(&g_elist[off + i + half]);
        float4 v = *(const float4*)(basep + (size_t)src * 128);
        s.x += v.x; s.y += v.y; s.z += v.z; s.w += v.w;
    }
    if (i < dr && half == 0) {        // odd tail
        int src = __ldg(&g_elist[off + i]);
        float4 v = *(const float4*)(basep + (size_t)src * 128);
        s.x += v.x; s.y += v.y; s.z += v.z; s.w += v.w;
    }
    s.x += __shfl_xor_sync(0xffffffffu, s.x, 16);
    s.y += __shfl_xor_sync(0xffffffffu, s.y, 16);
    s.z += __shfl_xor_sync(0xffffffffu, s.z, 16);
    s.w += __shfl_xor_sync(0xffffffffu, s.w, 16);
    if (half == 0) {
        float inv = (d > 0) ? (1.f / (float)d) : 0.f;
        float4 r = *(const float4*)(g_P2 + (size_t)w * 128 + 64 + sub * 4);
        float4 b = *(const float4*)(bias + sub * 4);
        float4 o;
        o.x = s.x * inv + r.x + b.x;
        o.y = s.y * inv + r.y + b.y;
        o.z = s.z * inv + r.z + b.z;
        o.w = s.w * inv + r.w + b.w;
        *(float4*)(outp + (size_t)w * 64 + sub * 4) = o;
    }
}

// ---------------- FUSED double GEMM (tf32 m16n8k8), software-pipelined ----
// Phase 1: acc = [agg | x] @ B1 (K=256); A tiles rotate through the 4 H
//          chunks (free 4-deep buffer), B1 double-buffered. One sync/tile.
// Epilogue 1: h = relu(acc + b1) -> H chunks (tf32).  h never hits DRAM.
// Phase 2: P2 = h_smem @ B2 (K=128), B2 double-buffered.
__global__ void __launch_bounds__(256, 2)
gemm_fused(const float* __restrict__ x_ext, const float* __restrict__ bias) {
    constexpr int BN  = 128;
    constexpr int WN  = 4;
    constexpr int WMT = 64;
    constexpr int WNT = 32;
    constexpr int MT  = 4;
    constexpr int NT  = 4;
    constexpr int BM = 128;
    constexpr int BK = 32;
    constexpr int ASTRIDE = BK + 4;               // 36
    constexpr int BSTRIDE = BN + 4;               // 132
    constexpr int CHUNK = BM * ASTRIDE;           // 4608 floats
    constexpr int BSZ   = BK * BSTRIDE;           // 4224 floats

    extern __shared__ float sm[];
    float* H = sm;                                // 4 * CHUNK
    float* Bsb[2] = { sm + 4 * CHUNK, sm + 4 * CHUNK + BSZ };

    int t    = threadIdx.x;
    int wid  = t >> 5;
    int lane = t & 31;
    int lr   = lane >> 2;                 // 0..7
    int lc   = lane & 3;                  // 0..3
    int warp_m = wid / WN;
    int warp_n = wid % WN;
    int m0 = blockIdx.x * BM;

    // stage phase-1 A tile `tile` (kc = tile*32) into H chunk (tile&3)
    auto stage_A = [&](int tile) {
        int kc = tile * BK;
        const float* Asrc = (kc < 128) ? g_agg : x_ext;
        int kbase = (kc < 128) ? kc : (kc - 128);
        float* dstc = H + (tile & 3) * CHUNK;
#pragma unroll
        for (int q = 0; q < 4; q++) {
            int idx  = t + q * 256;           // 0..1023
            int row  = idx >> 3;
            int c4   = (idx & 7) * 4;
            int node = m0 + row;
            float4 v = make_float4(0.f, 0.f, 0.f, 0.f);
            if (node < N_NODES)
                v = *(const float4*)(Asrc + (size_t)node * 128 + kbase + c4);
            float* dst = &dstc[row * ASTRIDE + c4];
            dst[0] = tf32r(v.x); dst[1] = tf32r(v.y);
            dst[2] = tf32r(v.z); dst[3] = tf32r(v.w);
        }
    };
    // stage B tile from Bmat (row offset kc) into buffer b
    auto stage_B = [&](const float* Bmat, int kc, float* Bsd) {
#pragma unroll
        for (int q = 0; q < 4; q++) {
            int idx  = t + q * 256;
            int kk   = idx >> 5;              // 32 float4 per k-row
            int col4 = idx & 31;
            *(float4*)&Bsd[kk * BSTRIDE + col4 * 4] =
                *(const float4*)(Bmat + (size_t)(kc + kk) * BN + col4 * 4);
        }
    };

    float acc[MT][NT][4];
#pragma unroll
    for (int i = 0; i < MT; i++)
#pragma unroll
        for (int j = 0; j < NT; j++)
#pragma unroll
            for (int q = 0; q < 4; q++) acc[i][j][q] = 0.f;

    // compute one 32-k tile from (As, Bs)
    auto compute = [&](const float* As, const float* Bs) {
#pragma unroll
        for (int ks = 0; ks < 4; ks++) {
            int kk = ks * 8;
            unsigned a[MT][4];
#pragma unroll
            for (int mt = 0; mt < MT; mt++) {
                const float* ap = &As[(warp_m * WMT + mt * 16 + lr) * ASTRIDE + kk + lc];
                a[mt][0] = __float_as_uint(ap[0]);
                a[mt][1] = __float_as_uint(ap[8 * ASTRIDE]);
                a[mt][2] = __float_as_uint(ap[4]);
                a[mt][3] = __float_as_uint(ap[8 * ASTRIDE + 4]);
            }
            unsigned b[NT][2];
#pragma unroll
            for (int nt = 0; nt < NT; nt++) {
                const float* bp = &Bs[(kk + lc) * BSTRIDE + warp_n * WNT + nt * 8 + lr];
                b[nt][0] = __float_as_uint(bp[0]);
                b[nt][1] = __float_as_uint(bp[4 * BSTRIDE]);
            }
#pragma unroll
            for (int mt = 0; mt < MT; mt++)
#pragma unroll
                for (int nt = 0; nt < NT; nt++) {
                    asm("mma.sync.aligned.m16n8k8.row.col.f32.tf32.tf32.f32 "
                        "{%0,%1,%2,%3}, {%4,%5,%6,%7}, {%8,%9}, {%0,%1,%2,%3};"
                        : "+f"(acc[mt][nt][0]), "+f"(acc[mt][nt][1]),
                          "+f"(acc[mt][nt][2]), "+f"(acc[mt][nt][3])
                        : "r"(a[mt][0]), "r"(a[mt][1]), "r"(a[mt][2]), "r"(a[mt][3]),
                          "r"(b[nt][0]), "r"(b[nt][1]));
                }
        }
    };

    // ================= phase 1: 8 tiles over B1, pipelined =================
    stage_A(0);
    stage_B(g_B1, 0, Bsb[0]);
    __syncthreads();
    for (int tile = 0; tile < 8; tile++) {
        if (tile < 7) {
            stage_A(tile + 1);
            stage_B(g_B1, (tile + 1) * BK, Bsb[(tile + 1) & 1]);
        }
        compute(H + (tile & 3) * CHUNK, Bsb[tile & 1]);
        __syncthreads();
    }

    // prefetch B2 tile 0 across the epilogue
    stage_B(g_B2, 0, Bsb[0]);

    // ---- epilogue 1: h = relu(acc + b1) -> SMEM (tf32-rounded), zero acc --
#pragma unroll
    for (int mt = 0; mt < MT; mt++) {
#pragma unroll
        for (int nt = 0; nt < NT; nt++) {
            int rl = warp_m * WMT + mt * 16 + lr;          // local row
            int c  = warp_n * WNT + nt * 8 + 2 * lc;       // h column (= k)
            float2 bv = *(const float2*)(bias + c);
            int ch = c >> 5;
            int cw = c & 31;
            float* h0 = &H[ch * CHUNK + rl * ASTRIDE + cw];
            h0[0] = tf32r(fmaxf(acc[mt][nt][0] + bv.x, 0.f));
            h0[1] = tf32r(fmaxf(acc[mt][nt][1] + bv.y, 0.f));
            float* h1 = h0 + 8 * ASTRIDE;
            h1[0] = tf32r(fmaxf(acc[mt][nt][2] + bv.x, 0.f));
            h1[1] = tf32r(fmaxf(acc[mt][nt][3] + bv.y, 0.f));
#pragma unroll
            for (int q = 0; q < 4; q++) acc[mt][nt][q] = 0.f;
        }
    }
    __syncthreads();

    // ================= phase 2: 4 tiles over B2, A = h in SMEM =============
    for (int tile = 0; tile < 4; tile++) {
        if (tile < 3)
            stage_B(g_B2, (tile + 1) * BK, Bsb[(tile + 1) & 1]);
        compute(H + tile * CHUNK, Bsb[tile & 1]);
        __syncthreads();
    }

    // ---- epilogue 2: store P2 ----
#pragma unroll
    for (int mt = 0; mt < MT; mt++) {
#pragma unroll
        for (int nt = 0; nt < NT; nt++) {
            int r = m0 + warp_m * WMT + mt * 16 + lr;
            int c = warp_n * WNT + nt * 8 + 2 * lc;
            if (r < N_NODES)
                *(float2*)(g_P2 + (size_t)r * BN + c) =
                    make_float2(acc[mt][nt][0], acc[mt][nt][1]);
            if (r + 8 < N_NODES)
                *(float2*)(g_P2 + (size_t)(r + 8) * BN + c) =
                    make_float2(acc[mt][nt][2], acc[mt][nt][3]);
        }
    }
}

// ---------------- launcher ----------------
extern "C" void kernel_launch(void* const* d_in, const int* in_sizes, int n_in,
                              void* d_out, int out_size) {
    const float* x   = (const float*)d_in[0];
    const int*   ei  = (const int*)d_in[1];       // int32 (JAX x64 disabled)
    const float* W1l = (const float*)d_in[2];
    const float* b1l = (const float*)d_in[3];
    const float* W1r = (const float*)d_in[4];
    const float* W2l = (const float*)d_in[5];
    const float* b2l = (const float*)d_in[6];
    const float* W2r = (const float*)d_in[7];
    float* out = (float*)d_out;

    const int T = 256;
    int g_prep = (256 * 128 + 128 * 128 + T - 1) / T;
    int g_edge = (N_EDGES + T - 1) / T;
    int g_aggr = (N_NODES * 32 + T - 1) / T;
    int g_gemm = (N_NODES + 127) / 128;

    // smem: H (4*4608) + 2x Bs (32*132) floats
    const int SMEM_BYTES = (4 * 128 * 36 + 2 * 32 * 132) * 4;   // 107520
    static int attr_done = 0;
    if (!attr_done) {
        cudaFuncSetAttribute(gemm_fused, cudaFuncAttributeMaxDynamicSharedMemorySize, SMEM_BYTES);
        attr_done = 1;
    }

    void* cntp = nullptr;
    cudaGetSymbolAddress(&cntp, g_cnt);
    cudaMemsetAsync(cntp, 0, N_NODES * sizeof(int));

    fill_buckets<<<g_edge, T>>>(ei);                   // kernel 1
    prep_weights<<<g_prep, T>>>(W1l, W1r, W2l, W2r);   // kernel 2
    aggregate<<<g_aggr, T>>>(x);                       // kernel 3
    gemm_fused<<<g_gemm, T, SMEM_BYTES>>>(x, b1l);     // kernel 4 (ncu-captured)
    aggregate_out<<<g_aggr, T>>>(b2l, out);            // kernel 5
}